// round 5
// baseline (speedup 1.0000x reference)
#include <cuda_runtime.h>
#include <cstdint>

// ---------------------------------------------------------------------------
// GRUCell: out = gru(LayerNorm(concat(x,h) @ W^T + b))
//   B=8192, IN=2048, H=4096, K=6144, N=3H=12288
//
// NOTE: harness compiles via compute_103 (non-'a') PTX: tcgen05/TMEM are
// ILLEGAL. Use portable mma.sync.m16n8k8.tf32 (fallback HMMA) + cp.async.
//
// Kernel 1: tf32 mma.sync GEMM (BM=128, BN=128, BK=16, 3-stage cp.async)
//           cvt.rna.tf32 on all fragments (truncation would bias ~1e-3)
// Kernel 2: per-row LayerNorm(12288) + GRU gates -> out[8192,4096]
// ---------------------------------------------------------------------------

#define B_ROWS   8192
#define IN_DIM   2048
#define H_DIM    4096
#define K_TOT    6144
#define N_TOT    12288

#define BM 128
#define BN 128
#define BK 16
#define STAGES 3
#define NK_TILES (K_TOT / BK)        // 384
#define MT (B_ROWS / BM)             // 64
#define NT (N_TOT / BN)              // 96
#define GROUP_M 8

#define LDA (BK + 4)                 // 20 floats: conflict-free frag loads
#define STAGE_FLOATS ((BM + BN) * LDA)          // 5120
#define GEMM_SMEM (STAGES * STAGE_FLOATS * 4)   // 61440 B

__device__ float g_parts[(size_t)B_ROWS * N_TOT];   // 402 MB scratch

// ------------------------------ helpers ------------------------------------
__device__ __forceinline__ uint32_t smem_u32(const void* p) {
    uint32_t a;
    asm("{ .reg .u64 t; cvta.to.shared.u64 t, %1; cvt.u32.u64 %0, t; }" : "=r"(a) : "l"(p));
    return a;
}
__device__ __forceinline__ void cp16(uint32_t s, const void* g) {
    asm volatile("cp.async.cg.shared.global [%0], [%1], 16;" :: "r"(s), "l"(g));
}
__device__ __forceinline__ uint32_t f2tf32(float f) {
    uint32_t r;
    asm("cvt.rna.tf32.f32 %0, %1;" : "=r"(r) : "f"(f));
    return r;
}
__device__ __forceinline__ void mma_tf32(float* d, const uint32_t* a, const uint32_t* b) {
    asm volatile(
        "mma.sync.aligned.m16n8k8.row.col.f32.tf32.tf32.f32 "
        "{%0,%1,%2,%3}, {%4,%5,%6,%7}, {%8,%9}, {%0,%1,%2,%3};"
        : "+f"(d[0]), "+f"(d[1]), "+f"(d[2]), "+f"(d[3])
        : "r"(a[0]), "r"(a[1]), "r"(a[2]), "r"(a[3]), "r"(b[0]), "r"(b[1]));
}

// --------------------------- tile load (cp.async) --------------------------
// A tile: 128 rows x 16 fp32 (row-major, k contiguous), padded rows of LDA.
// B tile: same shape from W (W is [N,K] row-major = col-major B: perfect).
__device__ __forceinline__ void load_tile(
    int kt, uint32_t a_base, uint32_t b_base,
    const float* __restrict__ inp, const float* __restrict__ st,
    const float* __restrict__ W, size_t rowA0, size_t rowB0, int tid)
{
    int ko = kt * BK;
    const float* aptr;
    size_t astride;
    if (ko < IN_DIM) { aptr = inp + ko;            astride = IN_DIM; }
    else             { aptr = st  + (ko - IN_DIM); astride = H_DIM;  }
    // 128 rows x 4 chunks of 16B = 512 tasks, 256 threads -> 2 each
    #pragma unroll
    for (int j = 0; j < 2; j++) {
        int idx = tid + j * 256;
        int row = idx >> 2, ck = idx & 3;
        cp16(a_base + (uint32_t)(row * LDA + ck * 4) * 4,
             aptr + (rowA0 + (size_t)row) * astride + ck * 4);
    }
    #pragma unroll
    for (int j = 0; j < 2; j++) {
        int idx = tid + j * 256;
        int row = idx >> 2, ck = idx & 3;
        cp16(b_base + (uint32_t)(row * LDA + ck * 4) * 4,
             W + (rowB0 + (size_t)row) * K_TOT + ko + ck * 4);
    }
}

// ------------------------------- GEMM kernel -------------------------------
extern __shared__ float dynsmem_f[];

__global__ __launch_bounds__(256, 2)
void gemm_tf32(const float* __restrict__ inp, const float* __restrict__ st,
               const float* __restrict__ W)
{
    uint32_t sb = smem_u32(dynsmem_f);
    int tid = threadIdx.x;
    int wid = tid >> 5, lane = tid & 31;
    int wm = wid >> 1, wn = wid & 1;          // 4 x 2 warp grid
    int lr = lane >> 2, lc = lane & 3;

    // L2-friendly rasterization: stripes of GROUP_M m-tiles, n fastest
    int bid = blockIdx.x;
    int g = bid / (GROUP_M * NT);
    int r = bid % (GROUP_M * NT);
    int tm = g * GROUP_M + (r % GROUP_M);
    int tn = r / GROUP_M;
    size_t rowA0 = (size_t)tm * BM;
    size_t rowB0 = (size_t)tn * BN;

    float acc[2][8][4];
    #pragma unroll
    for (int mi = 0; mi < 2; mi++)
        #pragma unroll
        for (int ni = 0; ni < 8; ni++)
            #pragma unroll
            for (int q = 0; q < 4; q++) acc[mi][ni][q] = 0.f;

    // prologue: stages 0,1
    #pragma unroll
    for (int t = 0; t < STAGES - 1; t++) {
        uint32_t ab = sb + t * STAGE_FLOATS * 4;
        load_tile(t, ab, ab + BM * LDA * 4, inp, st, W, rowA0, rowB0, tid);
        asm volatile("cp.async.commit_group;" ::: "memory");
    }

    for (int kt = 0; kt < NK_TILES; kt++) {
        int s = kt % STAGES;
        asm volatile("cp.async.wait_group 1;" ::: "memory");
        __syncthreads();

        // prefetch kt+2
        int tnext = kt + STAGES - 1;
        if (tnext < NK_TILES) {
            int sn = tnext % STAGES;
            uint32_t ab = sb + sn * STAGE_FLOATS * 4;
            load_tile(tnext, ab, ab + BM * LDA * 4, inp, st, W, rowA0, rowB0, tid);
        }
        asm volatile("cp.async.commit_group;" ::: "memory");

        const float* As = dynsmem_f + s * STAGE_FLOATS;
        const float* Bs = As + BM * LDA;

        #pragma unroll
        for (int ks = 0; ks < 2; ks++) {
            uint32_t af[2][4];
            #pragma unroll
            for (int mi = 0; mi < 2; mi++) {
                const float* ap = As + (wm * 32 + mi * 16 + lr) * LDA + ks * 8 + lc;
                af[mi][0] = f2tf32(ap[0]);
                af[mi][1] = f2tf32(ap[8 * LDA]);
                af[mi][2] = f2tf32(ap[4]);
                af[mi][3] = f2tf32(ap[8 * LDA + 4]);
            }
            uint32_t bf[8][2];
            #pragma unroll
            for (int ni = 0; ni < 8; ni++) {
                const float* bp = Bs + (wn * 64 + ni * 8 + lr) * LDA + ks * 8 + lc;
                bf[ni][0] = f2tf32(bp[0]);
                bf[ni][1] = f2tf32(bp[4]);
            }
            #pragma unroll
            for (int mi = 0; mi < 2; mi++)
                #pragma unroll
                for (int ni = 0; ni < 8; ni++)
                    mma_tf32(acc[mi][ni], af[mi], bf[ni]);
        }
    }

    // epilogue: direct stores (all bytes of each 256B row-segment are written)
    #pragma unroll
    for (int mi = 0; mi < 2; mi++) {
        size_t row0 = rowA0 + wm * 32 + mi * 16 + lr;
        #pragma unroll
        for (int ni = 0; ni < 8; ni++) {
            size_t col = rowB0 + wn * 64 + ni * 8 + 2 * lc;
            float2 v0 = make_float2(acc[mi][ni][0], acc[mi][ni][1]);
            float2 v1 = make_float2(acc[mi][ni][2], acc[mi][ni][3]);
            *reinterpret_cast<float2*>(g_parts + row0 * N_TOT + col) = v0;
            *reinterpret_cast<float2*>(g_parts + (row0 + 8) * N_TOT + col) = v1;
        }
    }
}

// --------------------------- LayerNorm + GRU gates -------------------------
extern __shared__ float lnsmem[];

__global__ __launch_bounds__(256)
void ln_gate(const float* __restrict__ st, const float* __restrict__ bias,
             const float* __restrict__ gam, const float* __restrict__ bet,
             float* __restrict__ out)
{
    float* rowbuf = lnsmem;                     // 12288 fp32
    __shared__ float wsum[8], wsum2[8];
    int tid = threadIdx.x;
    size_t rb = (size_t)blockIdx.x * N_TOT;

    float s = 0.f, s2 = 0.f;
    for (int i = tid * 4; i < N_TOT; i += 1024) {
        float4 v = *reinterpret_cast<const float4*>(g_parts + rb + i);
        float4 bb = *reinterpret_cast<const float4*>(bias + i);
        v.x += bb.x; v.y += bb.y; v.z += bb.z; v.w += bb.w;
        *reinterpret_cast<float4*>(rowbuf + i) = v;
        s += v.x + v.y + v.z + v.w;
        s2 += v.x * v.x + v.y * v.y + v.z * v.z + v.w * v.w;
    }
    #pragma unroll
    for (int o = 16; o; o >>= 1) {
        s  += __shfl_xor_sync(0xFFFFFFFFu, s,  o);
        s2 += __shfl_xor_sync(0xFFFFFFFFu, s2, o);
    }
    if ((tid & 31) == 0) { wsum[tid >> 5] = s; wsum2[tid >> 5] = s2; }
    __syncthreads();
    float S = 0.f, S2 = 0.f;
    #pragma unroll
    for (int w2 = 0; w2 < 8; w2++) { S += wsum[w2]; S2 += wsum2[w2]; }
    const float invN = 1.f / (float)N_TOT;
    float mu = S * invN;
    float var = S2 * invN - mu * mu;
    float rs = rsqrtf(var + 1e-5f);

    size_t ob = (size_t)blockIdx.x * H_DIM;
    for (int j = tid; j < H_DIM; j += 256) {
        float rr = (rowbuf[j]             - mu) * rs * gam[j]             + bet[j];
        float cc = (rowbuf[j + H_DIM]     - mu) * rs * gam[j + H_DIM]     + bet[j + H_DIM];
        float uu = (rowbuf[j + 2 * H_DIM] - mu) * rs * gam[j + 2 * H_DIM] + bet[j + 2 * H_DIM];
        float rg = 1.f / (1.f + expf(-rr));
        float cg = tanhf(rg * cc);
        float ug = 1.f / (1.f + expf(-(uu - 1.f)));   // UPDATE_BIAS = -1
        out[ob + j] = ug * cg + (1.f - ug) * st[ob + j];
    }
}

// ------------------------------ entry point --------------------------------
extern "C" void kernel_launch(void* const* d_in, const int* in_sizes, int n_in,
                              void* d_out, int out_size)
{
    const float* inp  = (const float*)d_in[0];   // [8192, 2048]
    const float* st   = (const float*)d_in[1];   // [8192, 4096]
    const float* W    = (const float*)d_in[2];   // [12288, 6144]
    const float* bias = (const float*)d_in[3];   // [12288]
    const float* gam  = (const float*)d_in[4];   // [12288]
    const float* bet  = (const float*)d_in[5];   // [12288]
    float* out = (float*)d_out;                  // [8192, 4096]

    cudaFuncSetAttribute(gemm_tf32, cudaFuncAttributeMaxDynamicSharedMemorySize, GEMM_SMEM);
    cudaFuncSetAttribute(ln_gate,   cudaFuncAttributeMaxDynamicSharedMemorySize, N_TOT * 4);

    gemm_tf32<<<MT * NT, 256, GEMM_SMEM>>>(inp, st, W);
    ln_gate<<<B_ROWS, 256, N_TOT * 4>>>(st, bias, gam, bet, out);
}

// round 6
// speedup vs baseline: 1.1611x; 1.1611x over previous
#include <cuda_runtime.h>
#include <cstdint>

// ---------------------------------------------------------------------------
// GRUCell: out = gru(LayerNorm(concat(x,h) @ W^T + b))
//   B=8192, IN=2048, H=4096, K=6144, N=3H=12288
//
// compute_103 PTX target: no tcgen05/TMEM. Register-path mma.sync tf32.
//
// R5: BM=128 BN=256 BK=32, warp tile 64x64 (1.0 LDS/MMA), 3-stage cp.async,
//     occ 1; ln_gate 512 threads vectorized.
// ---------------------------------------------------------------------------

#define B_ROWS   8192
#define IN_DIM   2048
#define H_DIM    4096
#define K_TOT    6144
#define N_TOT    12288

#define BM 128
#define BN 256
#define BK 32
#define STAGES 3
#define NK_TILES (K_TOT / BK)        // 192
#define MT (B_ROWS / BM)             // 64
#define NT (N_TOT / BN)              // 48
#define GROUP_M 8

#define LDA (BK + 4)                 // 36 floats: conflict-free frag reads
#define STAGE_FLOATS ((BM + BN) * LDA)          // 13824
#define GEMM_SMEM (STAGES * STAGE_FLOATS * 4)   // 165888 B

__device__ float g_parts[(size_t)B_ROWS * N_TOT];   // 402 MB scratch

// ------------------------------ helpers ------------------------------------
__device__ __forceinline__ uint32_t smem_u32(const void* p) {
    uint32_t a;
    asm("{ .reg .u64 t; cvta.to.shared.u64 t, %1; cvt.u32.u64 %0, t; }" : "=r"(a) : "l"(p));
    return a;
}
__device__ __forceinline__ void cp16(uint32_t s, const void* g) {
    asm volatile("cp.async.cg.shared.global [%0], [%1], 16;" :: "r"(s), "l"(g));
}
__device__ __forceinline__ uint32_t f2tf32(float f) {
    uint32_t r;
    asm("cvt.rna.tf32.f32 %0, %1;" : "=r"(r) : "f"(f));
    return r;
}
__device__ __forceinline__ void mma_tf32(float* d, const uint32_t* a, const uint32_t* b) {
    asm volatile(
        "mma.sync.aligned.m16n8k8.row.col.f32.tf32.tf32.f32 "
        "{%0,%1,%2,%3}, {%4,%5,%6,%7}, {%8,%9}, {%0,%1,%2,%3};"
        : "+f"(d[0]), "+f"(d[1]), "+f"(d[2]), "+f"(d[3])
        : "r"(a[0]), "r"(a[1]), "r"(a[2]), "r"(a[3]), "r"(b[0]), "r"(b[1]));
}

// --------------------------- tile load (cp.async) --------------------------
// A: 128 rows x 32 fp32 (k contiguous), pad LDA. IN_DIM multiple of BK, so
// every ktile comes entirely from inputs or entirely from state.
// B: 256 rows x 32 fp32 from W ([N,K] row-major = col-major operand).
__device__ __forceinline__ void load_tile(
    int kt, uint32_t a_base, uint32_t b_base,
    const float* __restrict__ inp, const float* __restrict__ st,
    const float* __restrict__ W, size_t rowA0, size_t rowB0, int tid)
{
    int ko = kt * BK;
    const float* aptr;
    size_t astride;
    if (ko < IN_DIM) { aptr = inp + ko;            astride = IN_DIM; }
    else             { aptr = st  + (ko - IN_DIM); astride = H_DIM;  }
    // A: 128 rows x 8 chunks = 1024 tasks, 256 threads -> 4 each
    #pragma unroll
    for (int j = 0; j < 4; j++) {
        int idx = tid + j * 256;
        int row = idx >> 3, ck = idx & 7;
        cp16(a_base + (uint32_t)(row * LDA + ck * 4) * 4,
             aptr + (rowA0 + (size_t)row) * astride + ck * 4);
    }
    // B: 256 rows x 8 chunks = 2048 tasks -> 8 each
    #pragma unroll
    for (int j = 0; j < 8; j++) {
        int idx = tid + j * 256;
        int row = idx >> 3, ck = idx & 7;
        cp16(b_base + (uint32_t)(row * LDA + ck * 4) * 4,
             W + (rowB0 + (size_t)row) * K_TOT + ko + ck * 4);
    }
}

// ------------------------------- GEMM kernel -------------------------------
extern __shared__ float dynsmem_f[];

__global__ __launch_bounds__(256, 1)
void gemm_tf32(const float* __restrict__ inp, const float* __restrict__ st,
               const float* __restrict__ W)
{
    uint32_t sb = smem_u32(dynsmem_f);
    int tid = threadIdx.x;
    int wid = tid >> 5, lane = tid & 31;
    int wm = wid >> 2, wn = wid & 3;          // 2 x 4 warp grid, 64x64 tiles
    int lr = lane >> 2, lc = lane & 3;

    // L2-friendly rasterization: stripes of GROUP_M m-tiles, n fastest
    int bid = blockIdx.x;
    int g = bid / (GROUP_M * NT);
    int r = bid % (GROUP_M * NT);
    int tm = g * GROUP_M + (r % GROUP_M);
    int tn = r / GROUP_M;
    size_t rowA0 = (size_t)tm * BM;
    size_t rowB0 = (size_t)tn * BN;

    float acc[4][8][4];
    #pragma unroll
    for (int mi = 0; mi < 4; mi++)
        #pragma unroll
        for (int ni = 0; ni < 8; ni++)
            #pragma unroll
            for (int q = 0; q < 4; q++) acc[mi][ni][q] = 0.f;

    // prologue: stages 0,1
    #pragma unroll
    for (int t = 0; t < STAGES - 1; t++) {
        uint32_t ab = sb + t * STAGE_FLOATS * 4;
        load_tile(t, ab, ab + BM * LDA * 4, inp, st, W, rowA0, rowB0, tid);
        asm volatile("cp.async.commit_group;" ::: "memory");
    }

    for (int kt = 0; kt < NK_TILES; kt++) {
        int s = kt % STAGES;
        asm volatile("cp.async.wait_group 1;" ::: "memory");
        __syncthreads();

        // prefetch kt+2
        int tnext = kt + STAGES - 1;
        if (tnext < NK_TILES) {
            int sn = tnext % STAGES;
            uint32_t ab = sb + sn * STAGE_FLOATS * 4;
            load_tile(tnext, ab, ab + BM * LDA * 4, inp, st, W, rowA0, rowB0, tid);
        }
        asm volatile("cp.async.commit_group;" ::: "memory");

        const float* As = dynsmem_f + s * STAGE_FLOATS;
        const float* Bs = As + BM * LDA;

        #pragma unroll
        for (int ks = 0; ks < 4; ks++) {
            uint32_t af[4][4];
            #pragma unroll
            for (int mi = 0; mi < 4; mi++) {
                const float* ap = As + (wm * 64 + mi * 16 + lr) * LDA + ks * 8 + lc;
                af[mi][0] = f2tf32(ap[0]);
                af[mi][1] = f2tf32(ap[8 * LDA]);
                af[mi][2] = f2tf32(ap[4]);
                af[mi][3] = f2tf32(ap[8 * LDA + 4]);
            }
            uint32_t bf[8][2];
            #pragma unroll
            for (int ni = 0; ni < 8; ni++) {
                const float* bp = Bs + (wn * 64 + ni * 8 + lr) * LDA + ks * 8 + lc;
                bf[ni][0] = f2tf32(bp[0]);
                bf[ni][1] = f2tf32(bp[4]);
            }
            #pragma unroll
            for (int mi = 0; mi < 4; mi++)
                #pragma unroll
                for (int ni = 0; ni < 8; ni++)
                    mma_tf32(acc[mi][ni], af[mi], bf[ni]);
        }
    }

    // epilogue: direct stores
    #pragma unroll
    for (int mi = 0; mi < 4; mi++) {
        size_t row0 = rowA0 + wm * 64 + mi * 16 + lr;
        #pragma unroll
        for (int ni = 0; ni < 8; ni++) {
            size_t col = rowB0 + wn * 64 + ni * 8 + 2 * lc;
            float2 v0 = make_float2(acc[mi][ni][0], acc[mi][ni][1]);
            float2 v1 = make_float2(acc[mi][ni][2], acc[mi][ni][3]);
            *reinterpret_cast<float2*>(g_parts + row0 * N_TOT + col) = v0;
            *reinterpret_cast<float2*>(g_parts + (row0 + 8) * N_TOT + col) = v1;
        }
    }
}

// --------------------------- LayerNorm + GRU gates -------------------------
extern __shared__ float lnsmem[];

__global__ __launch_bounds__(512)
void ln_gate(const float* __restrict__ st, const float* __restrict__ bias,
             const float* __restrict__ gam, const float* __restrict__ bet,
             float* __restrict__ out)
{
    float* rowbuf = lnsmem;                     // 12288 fp32
    __shared__ float wsum[16], wsum2[16];
    int tid = threadIdx.x;
    size_t rb = (size_t)blockIdx.x * N_TOT;

    float s = 0.f, s2 = 0.f;
    #pragma unroll 2
    for (int i = tid * 4; i < N_TOT; i += 2048) {
        float4 v = *reinterpret_cast<const float4*>(g_parts + rb + i);
        float4 bb = *reinterpret_cast<const float4*>(bias + i);
        v.x += bb.x; v.y += bb.y; v.z += bb.z; v.w += bb.w;
        *reinterpret_cast<float4*>(rowbuf + i) = v;
        s += v.x + v.y + v.z + v.w;
        s2 += v.x * v.x + v.y * v.y + v.z * v.z + v.w * v.w;
    }
    #pragma unroll
    for (int o = 16; o; o >>= 1) {
        s  += __shfl_xor_sync(0xFFFFFFFFu, s,  o);
        s2 += __shfl_xor_sync(0xFFFFFFFFu, s2, o);
    }
    if ((tid & 31) == 0) { wsum[tid >> 5] = s; wsum2[tid >> 5] = s2; }
    __syncthreads();
    float S = 0.f, S2 = 0.f;
    #pragma unroll
    for (int w2 = 0; w2 < 16; w2++) { S += wsum[w2]; S2 += wsum2[w2]; }
    const float invN = 1.f / (float)N_TOT;
    float mu = S * invN;
    float var = S2 * invN - mu * mu;
    float rs = rsqrtf(var + 1e-5f);

    size_t ob = (size_t)blockIdx.x * H_DIM;
    #pragma unroll 2
    for (int j = tid * 4; j < H_DIM; j += 2048) {
        float4 rv = *reinterpret_cast<const float4*>(rowbuf + j);
        float4 cv = *reinterpret_cast<const float4*>(rowbuf + j + H_DIM);
        float4 uv = *reinterpret_cast<const float4*>(rowbuf + j + 2 * H_DIM);
        float4 g0 = *reinterpret_cast<const float4*>(gam + j);
        float4 g1 = *reinterpret_cast<const float4*>(gam + j + H_DIM);
        float4 g2 = *reinterpret_cast<const float4*>(gam + j + 2 * H_DIM);
        float4 b0 = *reinterpret_cast<const float4*>(bet + j);
        float4 b1 = *reinterpret_cast<const float4*>(bet + j + H_DIM);
        float4 b2 = *reinterpret_cast<const float4*>(bet + j + 2 * H_DIM);
        float4 hv = *reinterpret_cast<const float4*>(st + ob + j);
        float4 ov;
        {
            float rr = (rv.x - mu) * rs * g0.x + b0.x;
            float cc = (cv.x - mu) * rs * g1.x + b1.x;
            float uu = (uv.x - mu) * rs * g2.x + b2.x;
            float rg = 1.f / (1.f + expf(-rr));
            float cg = tanhf(rg * cc);
            float ug = 1.f / (1.f + expf(-(uu - 1.f)));
            ov.x = ug * cg + (1.f - ug) * hv.x;
        }
        {
            float rr = (rv.y - mu) * rs * g0.y + b0.y;
            float cc = (cv.y - mu) * rs * g1.y + b1.y;
            float uu = (uv.y - mu) * rs * g2.y + b2.y;
            float rg = 1.f / (1.f + expf(-rr));
            float cg = tanhf(rg * cc);
            float ug = 1.f / (1.f + expf(-(uu - 1.f)));
            ov.y = ug * cg + (1.f - ug) * hv.y;
        }
        {
            float rr = (rv.z - mu) * rs * g0.z + b0.z;
            float cc = (cv.z - mu) * rs * g1.z + b1.z;
            float uu = (uv.z - mu) * rs * g2.z + b2.z;
            float rg = 1.f / (1.f + expf(-rr));
            float cg = tanhf(rg * cc);
            float ug = 1.f / (1.f + expf(-(uu - 1.f)));
            ov.z = ug * cg + (1.f - ug) * hv.z;
        }
        {
            float rr = (rv.w - mu) * rs * g0.w + b0.w;
            float cc = (cv.w - mu) * rs * g1.w + b1.w;
            float uu = (uv.w - mu) * rs * g2.w + b2.w;
            float rg = 1.f / (1.f + expf(-rr));
            float cg = tanhf(rg * cc);
            float ug = 1.f / (1.f + expf(-(uu - 1.f)));
            ov.w = ug * cg + (1.f - ug) * hv.w;
        }
        *reinterpret_cast<float4*>(out + ob + j) = ov;
    }
}

// ------------------------------ entry point --------------------------------
extern "C" void kernel_launch(void* const* d_in, const int* in_sizes, int n_in,
                              void* d_out, int out_size)
{
    const float* inp  = (const float*)d_in[0];   // [8192, 2048]
    const float* st   = (const float*)d_in[1];   // [8192, 4096]
    const float* W    = (const float*)d_in[2];   // [12288, 6144]
    const float* bias = (const float*)d_in[3];   // [12288]
    const float* gam  = (const float*)d_in[4];   // [12288]
    const float* bet  = (const float*)d_in[5];   // [12288]
    float* out = (float*)d_out;                  // [8192, 4096]

    cudaFuncSetAttribute(gemm_tf32, cudaFuncAttributeMaxDynamicSharedMemorySize, GEMM_SMEM);
    cudaFuncSetAttribute(ln_gate,   cudaFuncAttributeMaxDynamicSharedMemorySize, N_TOT * 4);

    gemm_tf32<<<MT * NT, 256, GEMM_SMEM>>>(inp, st, W);
    ln_gate<<<B_ROWS, 512, N_TOT * 4>>>(st, bias, gam, bet, out);
}

// round 7
// speedup vs baseline: 2.4651x; 2.1231x over previous
#include <cuda_runtime.h>
#include <cuda_fp16.h>
#include <cstdint>

// ---------------------------------------------------------------------------
// GRUCell: out = gru(LayerNorm(concat(x,h) @ W^T + b))
//   B=8192, IN=2048, H=4096, K=6144, N=3H=12288
//
// compute_103 PTX target: no tcgen05/TMEM. Register-path mma.sync.
//
// R6: fp16 operands (same 10-bit mantissa as tf32 => same accuracy) with
//     mma.sync.m16n8k16 = 2x FLOP/instr at same issue rate.
//     Convert x,h,W -> fp16 planes first (~110us), then fp16 GEMM
//     BM=128 BN=256 BK=64, warp tile 64x64, 3-stage cp.async.
// ---------------------------------------------------------------------------

#define B_ROWS   8192
#define IN_DIM   2048
#define H_DIM    4096
#define K_TOT    6144
#define N_TOT    12288

#define BM 128
#define BN 256
#define BK 64
#define STAGES 3
#define NK_TILES (K_TOT / BK)        // 96
#define MT (B_ROWS / BM)             // 64
#define NT (N_TOT / BN)              // 48
#define GROUP_M 8

#define LDA (BK + 8)                 // 72 halves: stride 36 words == 4 mod 32 -> conflict-free
#define A_STAGE_BYTES (BM * LDA * 2)            // 18432
#define B_STAGE_BYTES (BN * LDA * 2)            // 36864
#define STAGE_BYTES (A_STAGE_BYTES + B_STAGE_BYTES)   // 55296
#define GEMM_SMEM (STAGES * STAGE_BYTES)        // 165888 B

__device__ __half g_a[(size_t)B_ROWS * K_TOT];      // 100.7 MB fp16 [x|h]
__device__ __half g_w[(size_t)N_TOT * K_TOT];       // 151 MB fp16 W
__device__ float  g_parts[(size_t)B_ROWS * N_TOT];  // 402 MB fp32 GEMM out

// ------------------------------ helpers ------------------------------------
__device__ __forceinline__ uint32_t smem_u32(const void* p) {
    uint32_t a;
    asm("{ .reg .u64 t; cvta.to.shared.u64 t, %1; cvt.u32.u64 %0, t; }" : "=r"(a) : "l"(p));
    return a;
}
__device__ __forceinline__ void cp16(uint32_t s, const void* g) {
    asm volatile("cp.async.cg.shared.global [%0], [%1], 16;" :: "r"(s), "l"(g));
}
__device__ __forceinline__ void mma_f16(float* d, const uint32_t* a, const uint32_t* b) {
    asm volatile(
        "mma.sync.aligned.m16n8k16.row.col.f32.f16.f16.f32 "
        "{%0,%1,%2,%3}, {%4,%5,%6,%7}, {%8,%9}, {%0,%1,%2,%3};"
        : "+f"(d[0]), "+f"(d[1]), "+f"(d[2]), "+f"(d[3])
        : "r"(a[0]), "r"(a[1]), "r"(a[2]), "r"(a[3]), "r"(b[0]), "r"(b[1]));
}

// --------------------------- conversion kernels ----------------------------
// g_a[row, 0:2048) = fp16(x[row]);  g_a[row, 2048:6144) = fp16(h[row])
__global__ __launch_bounds__(256)
void cvt_a(const float* __restrict__ x, const float* __restrict__ h)
{
    int row = blockIdx.x;
    __half* dst = g_a + (size_t)row * K_TOT;
    const float* xr = x + (size_t)row * IN_DIM;
    const float* hr = h + (size_t)row * H_DIM;
    #pragma unroll
    for (int it = 0; it < 6; it++) {
        int k = threadIdx.x * 4 + it * 1024;
        float4 v = (k < IN_DIM)
            ? *reinterpret_cast<const float4*>(xr + k)
            : *reinterpret_cast<const float4*>(hr + (k - IN_DIM));
        __half2 p0 = __floats2half2_rn(v.x, v.y);
        __half2 p1 = __floats2half2_rn(v.z, v.w);
        *reinterpret_cast<uint2*>(dst + k) =
            make_uint2(*reinterpret_cast<uint32_t*>(&p0), *reinterpret_cast<uint32_t*>(&p1));
    }
}

__global__ __launch_bounds__(256)
void cvt_w(const float* __restrict__ W)
{
    size_t i = ((size_t)blockIdx.x * 256 + threadIdx.x) * 8;
    float4 v0 = *reinterpret_cast<const float4*>(W + i);
    float4 v1 = *reinterpret_cast<const float4*>(W + i + 4);
    __half2 p0 = __floats2half2_rn(v0.x, v0.y);
    __half2 p1 = __floats2half2_rn(v0.z, v0.w);
    __half2 p2 = __floats2half2_rn(v1.x, v1.y);
    __half2 p3 = __floats2half2_rn(v1.z, v1.w);
    *reinterpret_cast<uint4*>(g_w + i) = make_uint4(
        *reinterpret_cast<uint32_t*>(&p0), *reinterpret_cast<uint32_t*>(&p1),
        *reinterpret_cast<uint32_t*>(&p2), *reinterpret_cast<uint32_t*>(&p3));
}

// --------------------------- tile load (cp.async) --------------------------
// A: 128 rows x 64 fp16 (k contiguous) from g_a; B: 256 rows x 64 fp16 from g_w.
__device__ __forceinline__ void load_tile(
    int kt, uint32_t a_base, uint32_t b_base, size_t rowA0, size_t rowB0, int tid)
{
    int ko = kt * BK;
    // A: 128 rows x 8 chunks(16B) = 1024 tasks, 256 threads -> 4 each
    #pragma unroll
    for (int j = 0; j < 4; j++) {
        int idx = tid + j * 256;
        int row = idx >> 3, ck = idx & 7;
        cp16(a_base + (uint32_t)(row * LDA + ck * 8) * 2,
             g_a + (rowA0 + (size_t)row) * K_TOT + ko + ck * 8);
    }
    // B: 256 rows x 8 chunks = 2048 tasks -> 8 each
    #pragma unroll
    for (int j = 0; j < 8; j++) {
        int idx = tid + j * 256;
        int row = idx >> 3, ck = idx & 7;
        cp16(b_base + (uint32_t)(row * LDA + ck * 8) * 2,
             g_w + (rowB0 + (size_t)row) * K_TOT + ko + ck * 8);
    }
}

// ------------------------------- GEMM kernel -------------------------------
extern __shared__ __half dynsmem_h[];

__global__ __launch_bounds__(256, 1)
void gemm_f16(void)
{
    uint32_t sb = smem_u32(dynsmem_h);
    int tid = threadIdx.x;
    int wid = tid >> 5, lane = tid & 31;
    int wm = wid >> 2, wn = wid & 3;          // 2 x 4 warp grid, 64x64 warp tiles
    int lr = lane >> 2, lc = lane & 3;

    // L2-friendly rasterization: stripes of GROUP_M m-tiles, n fastest
    int bid = blockIdx.x;
    int g = bid / (GROUP_M * NT);
    int r = bid % (GROUP_M * NT);
    int tm = g * GROUP_M + (r % GROUP_M);
    int tn = r / GROUP_M;
    size_t rowA0 = (size_t)tm * BM;
    size_t rowB0 = (size_t)tn * BN;

    float acc[4][8][4];
    #pragma unroll
    for (int mi = 0; mi < 4; mi++)
        #pragma unroll
        for (int ni = 0; ni < 8; ni++)
            #pragma unroll
            for (int q = 0; q < 4; q++) acc[mi][ni][q] = 0.f;

    #pragma unroll
    for (int t = 0; t < STAGES - 1; t++) {
        uint32_t ab = sb + t * STAGE_BYTES;
        load_tile(t, ab, ab + A_STAGE_BYTES, rowA0, rowB0, tid);
        asm volatile("cp.async.commit_group;" ::: "memory");
    }

    for (int kt = 0; kt < NK_TILES; kt++) {
        int s = kt % STAGES;
        asm volatile("cp.async.wait_group 1;" ::: "memory");
        __syncthreads();

        int tnext = kt + STAGES - 1;
        if (tnext < NK_TILES) {
            int sn = tnext % STAGES;
            uint32_t ab = sb + sn * STAGE_BYTES;
            load_tile(tnext, ab, ab + A_STAGE_BYTES, rowA0, rowB0, tid);
        }
        asm volatile("cp.async.commit_group;" ::: "memory");

        const __half* As = dynsmem_h + s * (STAGE_BYTES / 2);
        const __half* Bs = As + BM * LDA;

        #pragma unroll
        for (int ks = 0; ks < 4; ks++) {               // BK=64 -> 4 x k16 steps
            uint32_t af[4][4];
            #pragma unroll
            for (int mi = 0; mi < 4; mi++) {
                const __half* ap = As + (wm * 64 + mi * 16 + lr) * LDA + ks * 16 + 2 * lc;
                af[mi][0] = *reinterpret_cast<const uint32_t*>(ap);
                af[mi][1] = *reinterpret_cast<const uint32_t*>(ap + 8 * LDA);
                af[mi][2] = *reinterpret_cast<const uint32_t*>(ap + 8);
                af[mi][3] = *reinterpret_cast<const uint32_t*>(ap + 8 * LDA + 8);
            }
            uint32_t bf[8][2];
            #pragma unroll
            for (int ni = 0; ni < 8; ni++) {
                const __half* bp = Bs + (wn * 64 + ni * 8 + lr) * LDA + ks * 16 + 2 * lc;
                bf[ni][0] = *reinterpret_cast<const uint32_t*>(bp);
                bf[ni][1] = *reinterpret_cast<const uint32_t*>(bp + 8);
            }
            #pragma unroll
            for (int mi = 0; mi < 4; mi++)
                #pragma unroll
                for (int ni = 0; ni < 8; ni++)
                    mma_f16(acc[mi][ni], af[mi], bf[ni]);
        }
    }

    // epilogue: direct stores to g_parts
    #pragma unroll
    for (int mi = 0; mi < 4; mi++) {
        size_t row0 = rowA0 + wm * 64 + mi * 16 + lr;
        #pragma unroll
        for (int ni = 0; ni < 8; ni++) {
            size_t col = rowB0 + wn * 64 + ni * 8 + 2 * lc;
            float2 v0 = make_float2(acc[mi][ni][0], acc[mi][ni][1]);
            float2 v1 = make_float2(acc[mi][ni][2], acc[mi][ni][3]);
            *reinterpret_cast<float2*>(g_parts + row0 * N_TOT + col) = v0;
            *reinterpret_cast<float2*>(g_parts + (row0 + 8) * N_TOT + col) = v1;
        }
    }
}

// --------------------------- LayerNorm + GRU gates -------------------------
extern __shared__ float lnsmem[];

__global__ __launch_bounds__(512)
void ln_gate(const float* __restrict__ st, const float* __restrict__ bias,
             const float* __restrict__ gam, const float* __restrict__ bet,
             float* __restrict__ out)
{
    float* rowbuf = lnsmem;                     // 12288 fp32
    __shared__ float wsum[16], wsum2[16];
    int tid = threadIdx.x;
    size_t rb = (size_t)blockIdx.x * N_TOT;

    float s = 0.f, s2 = 0.f;
    #pragma unroll 2
    for (int i = tid * 4; i < N_TOT; i += 2048) {
        float4 v = *reinterpret_cast<const float4*>(g_parts + rb + i);
        float4 bb = *reinterpret_cast<const float4*>(bias + i);
        v.x += bb.x; v.y += bb.y; v.z += bb.z; v.w += bb.w;
        *reinterpret_cast<float4*>(rowbuf + i) = v;
        s += v.x + v.y + v.z + v.w;
        s2 += v.x * v.x + v.y * v.y + v.z * v.z + v.w * v.w;
    }
    #pragma unroll
    for (int o = 16; o; o >>= 1) {
        s  += __shfl_xor_sync(0xFFFFFFFFu, s,  o);
        s2 += __shfl_xor_sync(0xFFFFFFFFu, s2, o);
    }
    if ((tid & 31) == 0) { wsum[tid >> 5] = s; wsum2[tid >> 5] = s2; }
    __syncthreads();
    float S = 0.f, S2 = 0.f;
    #pragma unroll
    for (int w2 = 0; w2 < 16; w2++) { S += wsum[w2]; S2 += wsum2[w2]; }
    const float invN = 1.f / (float)N_TOT;
    float mu = S * invN;
    float var = S2 * invN - mu * mu;
    float rs = rsqrtf(var + 1e-5f);

    size_t ob = (size_t)blockIdx.x * H_DIM;
    #pragma unroll 2
    for (int j = tid * 4; j < H_DIM; j += 2048) {
        float4 rv = *reinterpret_cast<const float4*>(rowbuf + j);
        float4 cv = *reinterpret_cast<const float4*>(rowbuf + j + H_DIM);
        float4 uv = *reinterpret_cast<const float4*>(rowbuf + j + 2 * H_DIM);
        float4 g0 = *reinterpret_cast<const float4*>(gam + j);
        float4 g1 = *reinterpret_cast<const float4*>(gam + j + H_DIM);
        float4 g2 = *reinterpret_cast<const float4*>(gam + j + 2 * H_DIM);
        float4 b0 = *reinterpret_cast<const float4*>(bet + j);
        float4 b1 = *reinterpret_cast<const float4*>(bet + j + H_DIM);
        float4 b2 = *reinterpret_cast<const float4*>(bet + j + 2 * H_DIM);
        float4 hv = *reinterpret_cast<const float4*>(st + ob + j);
        float4 ov;
        {
            float rr = (rv.x - mu) * rs * g0.x + b0.x;
            float cc = (cv.x - mu) * rs * g1.x + b1.x;
            float uu = (uv.x - mu) * rs * g2.x + b2.x;
            float rg = 1.f / (1.f + expf(-rr));
            float cg = tanhf(rg * cc);
            float ug = 1.f / (1.f + expf(-(uu - 1.f)));
            ov.x = ug * cg + (1.f - ug) * hv.x;
        }
        {
            float rr = (rv.y - mu) * rs * g0.y + b0.y;
            float cc = (cv.y - mu) * rs * g1.y + b1.y;
            float uu = (uv.y - mu) * rs * g2.y + b2.y;
            float rg = 1.f / (1.f + expf(-rr));
            float cg = tanhf(rg * cc);
            float ug = 1.f / (1.f + expf(-(uu - 1.f)));
            ov.y = ug * cg + (1.f - ug) * hv.y;
        }
        {
            float rr = (rv.z - mu) * rs * g0.z + b0.z;
            float cc = (cv.z - mu) * rs * g1.z + b1.z;
            float uu = (uv.z - mu) * rs * g2.z + b2.z;
            float rg = 1.f / (1.f + expf(-rr));
            float cg = tanhf(rg * cc);
            float ug = 1.f / (1.f + expf(-(uu - 1.f)));
            ov.z = ug * cg + (1.f - ug) * hv.z;
        }
        {
            float rr = (rv.w - mu) * rs * g0.w + b0.w;
            float cc = (cv.w - mu) * rs * g1.w + b1.w;
            float uu = (uv.w - mu) * rs * g2.w + b2.w;
            float rg = 1.f / (1.f + expf(-rr));
            float cg = tanhf(rg * cc);
            float ug = 1.f / (1.f + expf(-(uu - 1.f)));
            ov.w = ug * cg + (1.f - ug) * hv.w;
        }
        *reinterpret_cast<float4*>(out + ob + j) = ov;
    }
}

// ------------------------------ entry point --------------------------------
extern "C" void kernel_launch(void* const* d_in, const int* in_sizes, int n_in,
                              void* d_out, int out_size)
{
    const float* inp  = (const float*)d_in[0];   // [8192, 2048]
    const float* st   = (const float*)d_in[1];   // [8192, 4096]
    const float* W    = (const float*)d_in[2];   // [12288, 6144]
    const float* bias = (const float*)d_in[3];   // [12288]
    const float* gam  = (const float*)d_in[4];   // [12288]
    const float* bet  = (const float*)d_in[5];   // [12288]
    float* out = (float*)d_out;                  // [8192, 4096]

    cudaFuncSetAttribute(gemm_f16, cudaFuncAttributeMaxDynamicSharedMemorySize, GEMM_SMEM);
    cudaFuncSetAttribute(ln_gate,  cudaFuncAttributeMaxDynamicSharedMemorySize, N_TOT * 4);

    cvt_a<<<B_ROWS, 256>>>(inp, st);
    cvt_w<<<(int)(((size_t)N_TOT * K_TOT) / (256 * 8)), 256>>>(W);
    gemm_f16<<<MT * NT, 256, GEMM_SMEM>>>();
    ln_gate<<<B_ROWS, 512, N_TOT * 4>>>(st, bias, gam, bet, out);
}

// round 8
// speedup vs baseline: 2.4981x; 1.0134x over previous
#include <cuda_runtime.h>
#include <cuda_fp16.h>
#include <cstdint>

// ---------------------------------------------------------------------------
// GRUCell: out = gru(LayerNorm(concat(x,h) @ W^T + b))
//   B=8192, IN=2048, H=4096, K=6144, N=3H=12288
//
// compute_103 PTX target: no tcgen05/TMEM. Register-path mma.sync.
//
// R7: fp16 mma.sync m16n8k16 (rt=8 confirmed), ldmatrix.x4 fragment loads
//     (4x fewer LDS issues), 4-stage cp.async pipeline (221KB smem).
//     BM=128 BN=256 BK=64, warp tile 64x64.
// ---------------------------------------------------------------------------

#define B_ROWS   8192
#define IN_DIM   2048
#define H_DIM    4096
#define K_TOT    6144
#define N_TOT    12288

#define BM 128
#define BN 256
#define BK 64
#define STAGES 4
#define NK_TILES (K_TOT / BK)        // 96
#define MT (B_ROWS / BM)             // 64
#define NT (N_TOT / BN)              // 48
#define GROUP_M 8

#define LDA (BK + 8)                 // 72 halves; stride 36 words = 4 mod 32
#define A_STAGE_BYTES (BM * LDA * 2)            // 18432
#define B_STAGE_BYTES (BN * LDA * 2)            // 36864
#define STAGE_BYTES (A_STAGE_BYTES + B_STAGE_BYTES)   // 55296
#define GEMM_SMEM (STAGES * STAGE_BYTES)        // 221184 B

__device__ __half g_a[(size_t)B_ROWS * K_TOT];      // fp16 [x|h]
__device__ __half g_w[(size_t)N_TOT * K_TOT];       // fp16 W
__device__ float  g_parts[(size_t)B_ROWS * N_TOT];  // fp32 GEMM out

// ------------------------------ helpers ------------------------------------
__device__ __forceinline__ uint32_t smem_u32(const void* p) {
    uint32_t a;
    asm("{ .reg .u64 t; cvta.to.shared.u64 t, %1; cvt.u32.u64 %0, t; }" : "=r"(a) : "l"(p));
    return a;
}
__device__ __forceinline__ void cp16(uint32_t s, const void* g) {
    asm volatile("cp.async.cg.shared.global [%0], [%1], 16;" :: "r"(s), "l"(g));
}
__device__ __forceinline__ void mma_f16(float* d, const uint32_t* a, const uint32_t* b) {
    asm volatile(
        "mma.sync.aligned.m16n8k16.row.col.f32.f16.f16.f32 "
        "{%0,%1,%2,%3}, {%4,%5,%6,%7}, {%8,%9}, {%0,%1,%2,%3};"
        : "+f"(d[0]), "+f"(d[1]), "+f"(d[2]), "+f"(d[3])
        : "r"(a[0]), "r"(a[1]), "r"(a[2]), "r"(a[3]), "r"(b[0]), "r"(b[1]));
}
#define LDSM4(r0, r1, r2, r3, addr) \
    asm volatile("ldmatrix.sync.aligned.m8n8.x4.shared.b16 {%0,%1,%2,%3}, [%4];" \
        : "=r"(r0), "=r"(r1), "=r"(r2), "=r"(r3) : "r"(addr))

// --------------------------- conversion kernels ----------------------------
__global__ __launch_bounds__(256)
void cvt_a(const float* __restrict__ x, const float* __restrict__ h)
{
    int row = blockIdx.x;
    __half* dst = g_a + (size_t)row * K_TOT;
    const float* xr = x + (size_t)row * IN_DIM;
    const float* hr = h + (size_t)row * H_DIM;
    #pragma unroll
    for (int it = 0; it < 6; it++) {
        int k = threadIdx.x * 4 + it * 1024;
        float4 v = (k < IN_DIM)
            ? *reinterpret_cast<const float4*>(xr + k)
            : *reinterpret_cast<const float4*>(hr + (k - IN_DIM));
        __half2 p0 = __floats2half2_rn(v.x, v.y);
        __half2 p1 = __floats2half2_rn(v.z, v.w);
        *reinterpret_cast<uint2*>(dst + k) =
            make_uint2(*reinterpret_cast<uint32_t*>(&p0), *reinterpret_cast<uint32_t*>(&p1));
    }
}

__global__ __launch_bounds__(256)
void cvt_w(const float* __restrict__ W)
{
    size_t i = ((size_t)blockIdx.x * 256 + threadIdx.x) * 8;
    float4 v0 = *reinterpret_cast<const float4*>(W + i);
    float4 v1 = *reinterpret_cast<const float4*>(W + i + 4);
    __half2 p0 = __floats2half2_rn(v0.x, v0.y);
    __half2 p1 = __floats2half2_rn(v0.z, v0.w);
    __half2 p2 = __floats2half2_rn(v1.x, v1.y);
    __half2 p3 = __floats2half2_rn(v1.z, v1.w);
    *reinterpret_cast<uint4*>(g_w + i) = make_uint4(
        *reinterpret_cast<uint32_t*>(&p0), *reinterpret_cast<uint32_t*>(&p1),
        *reinterpret_cast<uint32_t*>(&p2), *reinterpret_cast<uint32_t*>(&p3));
}

// --------------------------- tile load (cp.async) --------------------------
__device__ __forceinline__ void load_tile(
    int kt, uint32_t a_base, uint32_t b_base, size_t rowA0, size_t rowB0, int tid)
{
    int ko = kt * BK;
    #pragma unroll
    for (int j = 0; j < 4; j++) {
        int idx = tid + j * 256;
        int row = idx >> 3, ck = idx & 7;
        cp16(a_base + (uint32_t)(row * LDA + ck * 8) * 2,
             g_a + (rowA0 + (size_t)row) * K_TOT + ko + ck * 8);
    }
    #pragma unroll
    for (int j = 0; j < 8; j++) {
        int idx = tid + j * 256;
        int row = idx >> 3, ck = idx & 7;
        cp16(b_base + (uint32_t)(row * LDA + ck * 8) * 2,
             g_w + (rowB0 + (size_t)row) * K_TOT + ko + ck * 8);
    }
}

// ------------------------------- GEMM kernel -------------------------------
extern __shared__ __half dynsmem_h[];

__global__ __launch_bounds__(256, 1)
void gemm_f16(void)
{
    uint32_t sb = smem_u32(dynsmem_h);
    int tid = threadIdx.x;
    int wid = tid >> 5, lane = tid & 31;
    int wm = wid >> 2, wn = wid & 3;          // 2 x 4 warp grid, 64x64 warp tiles
    int lr = lane >> 2, lc = lane & 3;
    int r8 = lane & 7, seg = lane >> 3;       // ldmatrix addressing

    int bid = blockIdx.x;
    int g = bid / (GROUP_M * NT);
    int r = bid % (GROUP_M * NT);
    int tm = g * GROUP_M + (r % GROUP_M);
    int tn = r / GROUP_M;
    size_t rowA0 = (size_t)tm * BM;
    size_t rowB0 = (size_t)tn * BN;

    // ldmatrix per-thread base offsets (in halves, within a stage)
    // A matrices: m0=(rows 0-7,k 0-7) m1=(rows 8-15,k 0-7) m2=(rows 0-7,k 8-15) m3=(8-15,8-15)
    uint32_t a_off0 = (uint32_t)((wm * 64 + r8 + (seg & 1) * 8) * LDA + (seg >> 1) * 8);
    // B matrices: m0=(n 0-7,k 0-7) m1=(n 0-7,k 8-15) m2=(n 8-15,k 0-7) m3=(n 8-15,k 8-15)
    uint32_t b_off0 = (uint32_t)((wn * 64 + r8 + (seg >> 1) * 8) * LDA + (seg & 1) * 8);

    float acc[4][8][4];
    #pragma unroll
    for (int mi = 0; mi < 4; mi++)
        #pragma unroll
        for (int ni = 0; ni < 8; ni++)
            #pragma unroll
            for (int q = 0; q < 4; q++) acc[mi][ni][q] = 0.f;

    #pragma unroll
    for (int t = 0; t < STAGES - 1; t++) {
        uint32_t ab = sb + t * STAGE_BYTES;
        load_tile(t, ab, ab + A_STAGE_BYTES, rowA0, rowB0, tid);
        asm volatile("cp.async.commit_group;" ::: "memory");
    }

    for (int kt = 0; kt < NK_TILES; kt++) {
        int s = kt % STAGES;
        asm volatile("cp.async.wait_group 2;" ::: "memory");
        __syncthreads();

        int tnext = kt + STAGES - 1;
        if (tnext < NK_TILES) {
            int sn = tnext % STAGES;
            uint32_t ab = sb + sn * STAGE_BYTES;
            load_tile(tnext, ab, ab + A_STAGE_BYTES, rowA0, rowB0, tid);
        }
        asm volatile("cp.async.commit_group;" ::: "memory");

        uint32_t As = sb + s * STAGE_BYTES;
        uint32_t Bs = As + A_STAGE_BYTES;

        #pragma unroll
        for (int ks = 0; ks < 4; ks++) {               // BK=64 -> 4 x k16 steps
            uint32_t af[4][4];
            #pragma unroll
            for (int mi = 0; mi < 4; mi++) {
                uint32_t addr = As + (a_off0 + (uint32_t)(mi * 16 * LDA + ks * 16)) * 2;
                LDSM4(af[mi][0], af[mi][1], af[mi][2], af[mi][3], addr);
            }
            uint32_t bf[8][2];
            #pragma unroll
            for (int np = 0; np < 4; np++) {
                uint32_t addr = Bs + (b_off0 + (uint32_t)(np * 16 * LDA + ks * 16)) * 2;
                LDSM4(bf[2 * np][0], bf[2 * np][1], bf[2 * np + 1][0], bf[2 * np + 1][1], addr);
            }
            #pragma unroll
            for (int mi = 0; mi < 4; mi++)
                #pragma unroll
                for (int ni = 0; ni < 8; ni++)
                    mma_f16(acc[mi][ni], af[mi], bf[ni]);
        }
    }

    // epilogue: direct stores to g_parts
    #pragma unroll
    for (int mi = 0; mi < 4; mi++) {
        size_t row0 = rowA0 + wm * 64 + mi * 16 + lr;
        #pragma unroll
        for (int ni = 0; ni < 8; ni++) {
            size_t col = rowB0 + wn * 64 + ni * 8 + 2 * lc;
            float2 v0 = make_float2(acc[mi][ni][0], acc[mi][ni][1]);
            float2 v1 = make_float2(acc[mi][ni][2], acc[mi][ni][3]);
            *reinterpret_cast<float2*>(g_parts + row0 * N_TOT + col) = v0;
            *reinterpret_cast<float2*>(g_parts + (row0 + 8) * N_TOT + col) = v1;
        }
    }
}

// --------------------------- LayerNorm + GRU gates -------------------------
extern __shared__ float lnsmem[];

__global__ __launch_bounds__(512)
void ln_gate(const float* __restrict__ st, const float* __restrict__ bias,
             const float* __restrict__ gam, const float* __restrict__ bet,
             float* __restrict__ out)
{
    float* rowbuf = lnsmem;                     // 12288 fp32
    __shared__ float wsum[16], wsum2[16];
    int tid = threadIdx.x;
    size_t rb = (size_t)blockIdx.x * N_TOT;

    float s = 0.f, s2 = 0.f;
    #pragma unroll 2
    for (int i = tid * 4; i < N_TOT; i += 2048) {
        float4 v = *reinterpret_cast<const float4*>(g_parts + rb + i);
        float4 bb = *reinterpret_cast<const float4*>(bias + i);
        v.x += bb.x; v.y += bb.y; v.z += bb.z; v.w += bb.w;
        *reinterpret_cast<float4*>(rowbuf + i) = v;
        s += v.x + v.y + v.z + v.w;
        s2 += v.x * v.x + v.y * v.y + v.z * v.z + v.w * v.w;
    }
    #pragma unroll
    for (int o = 16; o; o >>= 1) {
        s  += __shfl_xor_sync(0xFFFFFFFFu, s,  o);
        s2 += __shfl_xor_sync(0xFFFFFFFFu, s2, o);
    }
    if ((tid & 31) == 0) { wsum[tid >> 5] = s; wsum2[tid >> 5] = s2; }
    __syncthreads();
    float S = 0.f, S2 = 0.f;
    #pragma unroll
    for (int w2 = 0; w2 < 16; w2++) { S += wsum[w2]; S2 += wsum2[w2]; }
    const float invN = 1.f / (float)N_TOT;
    float mu = S * invN;
    float var = S2 * invN - mu * mu;
    float rs = rsqrtf(var + 1e-5f);

    size_t ob = (size_t)blockIdx.x * H_DIM;
    #pragma unroll 2
    for (int j = tid * 4; j < H_DIM; j += 2048) {
        float4 rv = *reinterpret_cast<const float4*>(rowbuf + j);
        float4 cv = *reinterpret_cast<const float4*>(rowbuf + j + H_DIM);
        float4 uv = *reinterpret_cast<const float4*>(rowbuf + j + 2 * H_DIM);
        float4 g0 = *reinterpret_cast<const float4*>(gam + j);
        float4 g1 = *reinterpret_cast<const float4*>(gam + j + H_DIM);
        float4 g2 = *reinterpret_cast<const float4*>(gam + j + 2 * H_DIM);
        float4 b0 = *reinterpret_cast<const float4*>(bet + j);
        float4 b1 = *reinterpret_cast<const float4*>(bet + j + H_DIM);
        float4 b2 = *reinterpret_cast<const float4*>(bet + j + 2 * H_DIM);
        float4 hv = *reinterpret_cast<const float4*>(st + ob + j);
        float4 ov;
        {
            float rr = (rv.x - mu) * rs * g0.x + b0.x;
            float cc = (cv.x - mu) * rs * g1.x + b1.x;
            float uu = (uv.x - mu) * rs * g2.x + b2.x;
            float rg = 1.f / (1.f + expf(-rr));
            float cg = tanhf(rg * cc);
            float ug = 1.f / (1.f + expf(-(uu - 1.f)));
            ov.x = ug * cg + (1.f - ug) * hv.x;
        }
        {
            float rr = (rv.y - mu) * rs * g0.y + b0.y;
            float cc = (cv.y - mu) * rs * g1.y + b1.y;
            float uu = (uv.y - mu) * rs * g2.y + b2.y;
            float rg = 1.f / (1.f + expf(-rr));
            float cg = tanhf(rg * cc);
            float ug = 1.f / (1.f + expf(-(uu - 1.f)));
            ov.y = ug * cg + (1.f - ug) * hv.y;
        }
        {
            float rr = (rv.z - mu) * rs * g0.z + b0.z;
            float cc = (cv.z - mu) * rs * g1.z + b1.z;
            float uu = (uv.z - mu) * rs * g2.z + b2.z;
            float rg = 1.f / (1.f + expf(-rr));
            float cg = tanhf(rg * cc);
            float ug = 1.f / (1.f + expf(-(uu - 1.f)));
            ov.z = ug * cg + (1.f - ug) * hv.z;
        }
        {
            float rr = (rv.w - mu) * rs * g0.w + b0.w;
            float cc = (cv.w - mu) * rs * g1.w + b1.w;
            float uu = (uv.w - mu) * rs * g2.w + b2.w;
            float rg = 1.f / (1.f + expf(-rr));
            float cg = tanhf(rg * cc);
            float ug = 1.f / (1.f + expf(-(uu - 1.f)));
            ov.w = ug * cg + (1.f - ug) * hv.w;
        }
        *reinterpret_cast<float4*>(out + ob + j) = ov;
    }
}

// ------------------------------ entry point --------------------------------
extern "C" void kernel_launch(void* const* d_in, const int* in_sizes, int n_in,
                              void* d_out, int out_size)
{
    const float* inp  = (const float*)d_in[0];   // [8192, 2048]
    const float* st   = (const float*)d_in[1];   // [8192, 4096]
    const float* W    = (const float*)d_in[2];   // [12288, 6144]
    const float* bias = (const float*)d_in[3];   // [12288]
    const float* gam  = (const float*)d_in[4];   // [12288]
    const float* bet  = (const float*)d_in[5];   // [12288]
    float* out = (float*)d_out;                  // [8192, 4096]

    cudaFuncSetAttribute(gemm_f16, cudaFuncAttributeMaxDynamicSharedMemorySize, GEMM_SMEM);
    cudaFuncSetAttribute(ln_gate,  cudaFuncAttributeMaxDynamicSharedMemorySize, N_TOT * 4);

    cvt_a<<<B_ROWS, 256>>>(inp, st);
    cvt_w<<<(int)(((size_t)N_TOT * K_TOT) / (256 * 8)), 256>>>(W);
    gemm_f16<<<MT * NT, 256, GEMM_SMEM>>>();
    ln_gate<<<B_ROWS, 512, N_TOT * 4>>>(st, bias, gam, bet, out);
}

// round 9
// speedup vs baseline: 2.6047x; 1.0427x over previous
#include <cuda_runtime.h>
#include <cuda_fp16.h>
#include <cstdint>

// ---------------------------------------------------------------------------
// GRUCell: out = gru(LayerNorm(concat(x,h) @ W^T + b))
//   B=8192, IN=2048, H=4096, K=6144, N=3H=12288
//
// compute_103 PTX target: no tcgen05/TMEM. Register-path mma.sync.
//
// R8: 512-thread GEMM CTA (4 warps/SMSP for latency hiding), warp tile 64x32,
//     BM=128 BN=256 BK=64, ldmatrix.x4, 4-stage cp.async.
// ---------------------------------------------------------------------------

#define B_ROWS   8192
#define IN_DIM   2048
#define H_DIM    4096
#define K_TOT    6144
#define N_TOT    12288

#define BM 128
#define BN 256
#define BK 64
#define STAGES 4
#define NK_TILES (K_TOT / BK)        // 96
#define MT (B_ROWS / BM)             // 64
#define NT (N_TOT / BN)              // 48
#define GROUP_M 8

#define LDA (BK + 8)                 // 72 halves; stride 36 words = 4 mod 32
#define A_STAGE_BYTES (BM * LDA * 2)            // 18432
#define B_STAGE_BYTES (BN * LDA * 2)            // 36864
#define STAGE_BYTES (A_STAGE_BYTES + B_STAGE_BYTES)   // 55296
#define GEMM_SMEM (STAGES * STAGE_BYTES)        // 221184 B

__device__ __half g_a[(size_t)B_ROWS * K_TOT];      // fp16 [x|h]
__device__ __half g_w[(size_t)N_TOT * K_TOT];       // fp16 W
__device__ float  g_parts[(size_t)B_ROWS * N_TOT];  // fp32 GEMM out

// ------------------------------ helpers ------------------------------------
__device__ __forceinline__ uint32_t smem_u32(const void* p) {
    uint32_t a;
    asm("{ .reg .u64 t; cvta.to.shared.u64 t, %1; cvt.u32.u64 %0, t; }" : "=r"(a) : "l"(p));
    return a;
}
__device__ __forceinline__ void cp16(uint32_t s, const void* g) {
    asm volatile("cp.async.cg.shared.global [%0], [%1], 16;" :: "r"(s), "l"(g));
}
__device__ __forceinline__ void mma_f16(float* d, const uint32_t* a, const uint32_t* b) {
    asm volatile(
        "mma.sync.aligned.m16n8k16.row.col.f32.f16.f16.f32 "
        "{%0,%1,%2,%3}, {%4,%5,%6,%7}, {%8,%9}, {%0,%1,%2,%3};"
        : "+f"(d[0]), "+f"(d[1]), "+f"(d[2]), "+f"(d[3])
        : "r"(a[0]), "r"(a[1]), "r"(a[2]), "r"(a[3]), "r"(b[0]), "r"(b[1]));
}
#define LDSM4(r0, r1, r2, r3, addr) \
    asm volatile("ldmatrix.sync.aligned.m8n8.x4.shared.b16 {%0,%1,%2,%3}, [%4];" \
        : "=r"(r0), "=r"(r1), "=r"(r2), "=r"(r3) : "r"(addr))

// --------------------------- conversion kernels ----------------------------
__global__ __launch_bounds__(256)
void cvt_a(const float* __restrict__ x, const float* __restrict__ h)
{
    int row = blockIdx.x;
    __half* dst = g_a + (size_t)row * K_TOT;
    const float* xr = x + (size_t)row * IN_DIM;
    const float* hr = h + (size_t)row * H_DIM;
    #pragma unroll
    for (int it = 0; it < 6; it++) {
        int k = threadIdx.x * 4 + it * 1024;
        float4 v = (k < IN_DIM)
            ? *reinterpret_cast<const float4*>(xr + k)
            : *reinterpret_cast<const float4*>(hr + (k - IN_DIM));
        __half2 p0 = __floats2half2_rn(v.x, v.y);
        __half2 p1 = __floats2half2_rn(v.z, v.w);
        *reinterpret_cast<uint2*>(dst + k) =
            make_uint2(*reinterpret_cast<uint32_t*>(&p0), *reinterpret_cast<uint32_t*>(&p1));
    }
}

__global__ __launch_bounds__(256)
void cvt_w(const float* __restrict__ W)
{
    size_t i = ((size_t)blockIdx.x * 256 + threadIdx.x) * 8;
    float4 v0 = *reinterpret_cast<const float4*>(W + i);
    float4 v1 = *reinterpret_cast<const float4*>(W + i + 4);
    __half2 p0 = __floats2half2_rn(v0.x, v0.y);
    __half2 p1 = __floats2half2_rn(v0.z, v0.w);
    __half2 p2 = __floats2half2_rn(v1.x, v1.y);
    __half2 p3 = __floats2half2_rn(v1.z, v1.w);
    *reinterpret_cast<uint4*>(g_w + i) = make_uint4(
        *reinterpret_cast<uint32_t*>(&p0), *reinterpret_cast<uint32_t*>(&p1),
        *reinterpret_cast<uint32_t*>(&p2), *reinterpret_cast<uint32_t*>(&p3));
}

// --------------------------- tile load (cp.async) --------------------------
// 512 threads: A 1024 chunks -> 2 each; B 2048 chunks -> 4 each.
__device__ __forceinline__ void load_tile(
    int kt, uint32_t a_base, uint32_t b_base, size_t rowA0, size_t rowB0, int tid)
{
    int ko = kt * BK;
    #pragma unroll
    for (int j = 0; j < 2; j++) {
        int idx = tid + j * 512;
        int row = idx >> 3, ck = idx & 7;
        cp16(a_base + (uint32_t)(row * LDA + ck * 8) * 2,
             g_a + (rowA0 + (size_t)row) * K_TOT + ko + ck * 8);
    }
    #pragma unroll
    for (int j = 0; j < 4; j++) {
        int idx = tid + j * 512;
        int row = idx >> 3, ck = idx & 7;
        cp16(b_base + (uint32_t)(row * LDA + ck * 8) * 2,
             g_w + (rowB0 + (size_t)row) * K_TOT + ko + ck * 8);
    }
}

// ------------------------------- GEMM kernel -------------------------------
extern __shared__ __half dynsmem_h[];

__global__ __launch_bounds__(512, 1)
void gemm_f16(void)
{
    uint32_t sb = smem_u32(dynsmem_h);
    int tid = threadIdx.x;
    int wid = tid >> 5, lane = tid & 31;
    int wm = wid >> 3, wn = wid & 7;          // 2 x 8 warp grid, 64x32 warp tiles
    int lr = lane >> 2, lc = lane & 3;
    int r8 = lane & 7, seg = lane >> 3;       // ldmatrix addressing

    int bid = blockIdx.x;
    int g = bid / (GROUP_M * NT);
    int r = bid % (GROUP_M * NT);
    int tm = g * GROUP_M + (r % GROUP_M);
    int tn = r / GROUP_M;
    size_t rowA0 = (size_t)tm * BM;
    size_t rowB0 = (size_t)tn * BN;

    // ldmatrix per-thread base offsets (in halves, within a stage)
    // A x4: m0=(rows 0-7,k0-7) m1=(rows 8-15,k0-7) m2=(rows 0-7,k8-15) m3=(8-15,8-15)
    uint32_t a_off0 = (uint32_t)((wm * 64 + r8 + (seg & 1) * 8) * LDA + (seg >> 1) * 8);
    // B x4: m0=(n 0-7,k0-7) m1=(n 0-7,k8-15) m2=(n 8-15,k0-7) m3=(n 8-15,k8-15)
    uint32_t b_off0 = (uint32_t)((wn * 32 + r8 + (seg >> 1) * 8) * LDA + (seg & 1) * 8);

    float acc[4][4][4];
    #pragma unroll
    for (int mi = 0; mi < 4; mi++)
        #pragma unroll
        for (int ni = 0; ni < 4; ni++)
            #pragma unroll
            for (int q = 0; q < 4; q++) acc[mi][ni][q] = 0.f;

    #pragma unroll
    for (int t = 0; t < STAGES - 1; t++) {
        uint32_t ab = sb + t * STAGE_BYTES;
        load_tile(t, ab, ab + A_STAGE_BYTES, rowA0, rowB0, tid);
        asm volatile("cp.async.commit_group;" ::: "memory");
    }

    for (int kt = 0; kt < NK_TILES; kt++) {
        int s = kt % STAGES;
        asm volatile("cp.async.wait_group 2;" ::: "memory");
        __syncthreads();

        int tnext = kt + STAGES - 1;
        if (tnext < NK_TILES) {
            int sn = tnext % STAGES;
            uint32_t ab = sb + sn * STAGE_BYTES;
            load_tile(tnext, ab, ab + A_STAGE_BYTES, rowA0, rowB0, tid);
        }
        asm volatile("cp.async.commit_group;" ::: "memory");

        uint32_t As = sb + s * STAGE_BYTES;
        uint32_t Bs = As + A_STAGE_BYTES;

        #pragma unroll
        for (int ks = 0; ks < 4; ks++) {               // BK=64 -> 4 x k16 steps
            uint32_t af[4][4];
            #pragma unroll
            for (int mi = 0; mi < 4; mi++) {
                uint32_t addr = As + (a_off0 + (uint32_t)(mi * 16 * LDA + ks * 16)) * 2;
                LDSM4(af[mi][0], af[mi][1], af[mi][2], af[mi][3], addr);
            }
            uint32_t bf[4][2];
            #pragma unroll
            for (int np = 0; np < 2; np++) {
                uint32_t addr = Bs + (b_off0 + (uint32_t)(np * 16 * LDA + ks * 16)) * 2;
                LDSM4(bf[2 * np][0], bf[2 * np][1], bf[2 * np + 1][0], bf[2 * np + 1][1], addr);
            }
            #pragma unroll
            for (int mi = 0; mi < 4; mi++)
                #pragma unroll
                for (int ni = 0; ni < 4; ni++)
                    mma_f16(acc[mi][ni], af[mi], bf[ni]);
        }
    }

    // epilogue: direct stores to g_parts
    #pragma unroll
    for (int mi = 0; mi < 4; mi++) {
        size_t row0 = rowA0 + wm * 64 + mi * 16 + lr;
        #pragma unroll
        for (int ni = 0; ni < 4; ni++) {
            size_t col = rowB0 + wn * 32 + ni * 8 + 2 * lc;
            float2 v0 = make_float2(acc[mi][ni][0], acc[mi][ni][1]);
            float2 v1 = make_float2(acc[mi][ni][2], acc[mi][ni][3]);
            *reinterpret_cast<float2*>(g_parts + row0 * N_TOT + col) = v0;
            *reinterpret_cast<float2*>(g_parts + (row0 + 8) * N_TOT + col) = v1;
        }
    }
}

// --------------------------- LayerNorm + GRU gates -------------------------
extern __shared__ float lnsmem[];

__global__ __launch_bounds__(512, 3)
void ln_gate(const float* __restrict__ st, const float* __restrict__ bias,
             const float* __restrict__ gam, const float* __restrict__ bet,
             float* __restrict__ out)
{
    float* rowbuf = lnsmem;                     // 12288 fp32
    __shared__ float wsum[16], wsum2[16];
    int tid = threadIdx.x;
    size_t rb = (size_t)blockIdx.x * N_TOT;

    float s = 0.f, s2 = 0.f;
    #pragma unroll 2
    for (int i = tid * 4; i < N_TOT; i += 2048) {
        float4 v = *reinterpret_cast<const float4*>(g_parts + rb + i);
        float4 bb = *reinterpret_cast<const float4*>(bias + i);
        v.x += bb.x; v.y += bb.y; v.z += bb.z; v.w += bb.w;
        *reinterpret_cast<float4*>(rowbuf + i) = v;
        s += v.x + v.y + v.z + v.w;
        s2 += v.x * v.x + v.y * v.y + v.z * v.z + v.w * v.w;
    }
    #pragma unroll
    for (int o = 16; o; o >>= 1) {
        s  += __shfl_xor_sync(0xFFFFFFFFu, s,  o);
        s2 += __shfl_xor_sync(0xFFFFFFFFu, s2, o);
    }
    if ((tid & 31) == 0) { wsum[tid >> 5] = s; wsum2[tid >> 5] = s2; }
    __syncthreads();
    float S = 0.f, S2 = 0.f;
    #pragma unroll
    for (int w2 = 0; w2 < 16; w2++) { S += wsum[w2]; S2 += wsum2[w2]; }
    const float invN = 1.f / (float)N_TOT;
    float mu = S * invN;
    float var = S2 * invN - mu * mu;
    float rs = rsqrtf(var + 1e-5f);

    size_t ob = (size_t)blockIdx.x * H_DIM;
    #pragma unroll 2
    for (int j = tid * 4; j < H_DIM; j += 2048) {
        float4 rv = *reinterpret_cast<const float4*>(rowbuf + j);
        float4 cv = *reinterpret_cast<const float4*>(rowbuf + j + H_DIM);
        float4 uv = *reinterpret_cast<const float4*>(rowbuf + j + 2 * H_DIM);
        float4 g0 = *reinterpret_cast<const float4*>(gam + j);
        float4 g1 = *reinterpret_cast<const float4*>(gam + j + H_DIM);
        float4 g2 = *reinterpret_cast<const float4*>(gam + j + 2 * H_DIM);
        float4 b0 = *reinterpret_cast<const float4*>(bet + j);
        float4 b1 = *reinterpret_cast<const float4*>(bet + j + H_DIM);
        float4 b2 = *reinterpret_cast<const float4*>(bet + j + 2 * H_DIM);
        float4 hv = *reinterpret_cast<const float4*>(st + ob + j);
        float4 ov;
        {
            float rr = (rv.x - mu) * rs * g0.x + b0.x;
            float cc = (cv.x - mu) * rs * g1.x + b1.x;
            float uu = (uv.x - mu) * rs * g2.x + b2.x;
            float rg = 1.f / (1.f + expf(-rr));
            float cg = tanhf(rg * cc);
            float ug = 1.f / (1.f + expf(-(uu - 1.f)));
            ov.x = ug * cg + (1.f - ug) * hv.x;
        }
        {
            float rr = (rv.y - mu) * rs * g0.y + b0.y;
            float cc = (cv.y - mu) * rs * g1.y + b1.y;
            float uu = (uv.y - mu) * rs * g2.y + b2.y;
            float rg = 1.f / (1.f + expf(-rr));
            float cg = tanhf(rg * cc);
            float ug = 1.f / (1.f + expf(-(uu - 1.f)));
            ov.y = ug * cg + (1.f - ug) * hv.y;
        }
        {
            float rr = (rv.z - mu) * rs * g0.z + b0.z;
            float cc = (cv.z - mu) * rs * g1.z + b1.z;
            float uu = (uv.z - mu) * rs * g2.z + b2.z;
            float rg = 1.f / (1.f + expf(-rr));
            float cg = tanhf(rg * cc);
            float ug = 1.f / (1.f + expf(-(uu - 1.f)));
            ov.z = ug * cg + (1.f - ug) * hv.z;
        }
        {
            float rr = (rv.w - mu) * rs * g0.w + b0.w;
            float cc = (cv.w - mu) * rs * g1.w + b1.w;
            float uu = (uv.w - mu) * rs * g2.w + b2.w;
            float rg = 1.f / (1.f + expf(-rr));
            float cg = tanhf(rg * cc);
            float ug = 1.f / (1.f + expf(-(uu - 1.f)));
            ov.w = ug * cg + (1.f - ug) * hv.w;
        }
        *reinterpret_cast<float4*>(out + ob + j) = ov;
    }
}

// ------------------------------ entry point --------------------------------
extern "C" void kernel_launch(void* const* d_in, const int* in_sizes, int n_in,
                              void* d_out, int out_size)
{
    const float* inp  = (const float*)d_in[0];   // [8192, 2048]
    const float* st   = (const float*)d_in[1];   // [8192, 4096]
    const float* W    = (const float*)d_in[2];   // [12288, 6144]
    const float* bias = (const float*)d_in[3];   // [12288]
    const float* gam  = (const float*)d_in[4];   // [12288]
    const float* bet  = (const float*)d_in[5];   // [12288]
    float* out = (float*)d_out;                  // [8192, 4096]

    cudaFuncSetAttribute(gemm_f16, cudaFuncAttributeMaxDynamicSharedMemorySize, GEMM_SMEM);
    cudaFuncSetAttribute(ln_gate,  cudaFuncAttributeMaxDynamicSharedMemorySize, N_TOT * 4);

    cvt_a<<<B_ROWS, 256>>>(inp, st);
    cvt_w<<<(int)(((size_t)N_TOT * K_TOT) / (256 * 8)), 256>>>(W);
    gemm_f16<<<MT * NT, 512, GEMM_SMEM>>>();
    ln_gate<<<B_ROWS, 512, N_TOT * 4>>>(st, bias, gam, bet, out);
}